// round 4
// baseline (speedup 1.0000x reference)
#include <cuda_runtime.h>
#include <cstdint>

#define NN 100000
#define EE 3200000
#define H 128

// ---------------- scratch (__device__ globals; allocation-free rule) ----------------
__device__ float g_X[(size_t)NN * H];   // 51.2 MB ping
__device__ float g_A[(size_t)NN * H];   // 51.2 MB pong
__device__ float g_dinv[NN];
__device__ int   g_deg[100352];         // padded for int4 zeroing
__device__ int   g_off[NN + 1];
__device__ int   g_cur[100352];
__device__ int   g_csrc[EE];            // CSR: src per incoming edge of dst
__device__ float g_cnrm[EE];            // CSR: norm per incoming edge
__device__ int   g_is64;

__device__ __forceinline__ float fast_tanh(float x) {
    float t = __expf(-2.0f * fabsf(x));
    float r = __fdividef(1.0f - t, 1.0f + t);
    return copysignf(r, x);
}

// ---------------- packed f32x2 helpers ----------------
__device__ __forceinline__ unsigned long long pack2(float lo, float hi) {
    unsigned long long r;
    asm("mov.b64 %0, {%1, %2};" : "=l"(r) : "f"(lo), "f"(hi));
    return r;
}
__device__ __forceinline__ unsigned long long fma2(unsigned long long a,
                                                   unsigned long long b,
                                                   unsigned long long c) {
    unsigned long long d;
    asm("fma.rn.f32x2 %0, %1, %2, %3;" : "=l"(d) : "l"(a), "l"(b), "l"(c));
    return d;
}
__device__ __forceinline__ float2 unpack2(unsigned long long v) {
    float2 f;
    asm("mov.b64 {%0, %1}, %2;" : "=f"(f.x), "=f"(f.y) : "l"(v));
    return f;
}

// ---------------- edge dtype detection (int32 vs int64) ----------------
__global__ void detect_k(const int* __restrict__ ei32) {
    __shared__ int nz;
    if (threadIdx.x == 0) nz = 0;
    __syncthreads();
    int c = 0;
    for (int k = threadIdx.x; k < 4096; k += blockDim.x)
        if (ei32[2 * k + 1] != 0) c++;
    atomicAdd(&nz, c);
    __syncthreads();
    if (threadIdx.x == 0) g_is64 = (nz == 0) ? 1 : 0;
}

__device__ __forceinline__ int edge_val(const void* ei, long long E, long long idx, int row) {
    if (g_is64) return (int)((const long long*)ei)[row ? E + idx : idx];
    return ((const int*)ei)[row ? E + idx : idx];
}

// ---------------- zero ints ----------------
__global__ void zeroi_k(int4* __restrict__ p, int n4) {
    int i = blockIdx.x * blockDim.x + threadIdx.x;
    if (i < n4) p[i] = make_int4(0, 0, 0, 0);
}

// ---------------- degree count ----------------
__global__ void deg_k(const void* __restrict__ ei, long long E, int* __restrict__ deg) {
    long long e = (long long)blockIdx.x * blockDim.x + threadIdx.x;
    if (e < E) atomicAdd(&deg[edge_val(ei, E, e, 1)], 1);
}

__global__ void dinv_k(const int* __restrict__ deg, float* __restrict__ dinv, int n) {
    int i = blockIdx.x * blockDim.x + threadIdx.x;
    if (i < n) dinv[i] = rsqrtf((float)deg[i] + 2.0f);   // improved self-loop: +2
}

// ---------------- single-block scan: deg -> off, cur ----------------
__global__ void __launch_bounds__(1024) scan_k(const int* __restrict__ deg,
                                               int* __restrict__ off,
                                               int* __restrict__ cur, int n) {
    __shared__ int part[1024];
    int t = threadIdx.x;
    int chunk = (n + 1023) / 1024;
    int lo = t * chunk, hi = lo + chunk < n ? lo + chunk : n;
    int s = 0;
    for (int i = lo; i < hi; i++) s += deg[i];
    part[t] = s;
    __syncthreads();
    for (int o = 1; o < 1024; o <<= 1) {
        int v = (t >= o) ? part[t - o] : 0;
        __syncthreads();
        part[t] += v;
        __syncthreads();
    }
    int base = (t == 0) ? 0 : part[t - 1];
    for (int i = lo; i < hi; i++) {
        off[i] = base; cur[i] = base; base += deg[i];
    }
    if (t == 0) off[n] = part[1023];
}

// ---------------- CSR fill ----------------
__global__ void fill_k(const void* __restrict__ ei, long long E,
                       const float* __restrict__ dinv,
                       int* __restrict__ cur, int* __restrict__ csrc,
                       float* __restrict__ cnrm) {
    long long e = (long long)blockIdx.x * blockDim.x + threadIdx.x;
    if (e >= E) return;
    int s = edge_val(ei, E, e, 0);
    int d = edge_val(ei, E, e, 1);
    int pos = atomicAdd(&cur[d], 1);
    csrc[pos] = s;
    cnrm[pos] = dinv[s] * dinv[d];
}

// ---------------- gather + conv epilogue: out = tanh(sum + xw*2dinv^2 + b) ----------------
__global__ void __launch_bounds__(256) aggregate_k(
    const float* __restrict__ xw, const int* __restrict__ off,
    const int* __restrict__ deg, const int* __restrict__ csrc,
    const float* __restrict__ cnrm, const float* __restrict__ dinv,
    const float* __restrict__ bias, float* __restrict__ out, int n)
{
    int node = (blockIdx.x * 256 + threadIdx.x) >> 5;
    int lane = threadIdx.x & 31;
    if (node >= n) return;
    int j = off[node];
    int end = j + deg[node];
    const float4* X4 = (const float4*)xw;
    float4 acc = make_float4(0.f, 0.f, 0.f, 0.f);
    // 4-wide unroll: keep 4 gathers in flight
    for (; j + 3 < end; j += 4) {
        int s0 = __ldg(&csrc[j]);     int s1 = __ldg(&csrc[j + 1]);
        int s2 = __ldg(&csrc[j + 2]); int s3 = __ldg(&csrc[j + 3]);
        float n0 = __ldg(&cnrm[j]);   float n1 = __ldg(&cnrm[j + 1]);
        float n2 = __ldg(&cnrm[j + 2]); float n3 = __ldg(&cnrm[j + 3]);
        float4 v0 = X4[(size_t)s0 * 32 + lane];
        float4 v1 = X4[(size_t)s1 * 32 + lane];
        float4 v2 = X4[(size_t)s2 * 32 + lane];
        float4 v3 = X4[(size_t)s3 * 32 + lane];
        acc.x = fmaf(v0.x, n0, acc.x); acc.y = fmaf(v0.y, n0, acc.y);
        acc.z = fmaf(v0.z, n0, acc.z); acc.w = fmaf(v0.w, n0, acc.w);
        acc.x = fmaf(v1.x, n1, acc.x); acc.y = fmaf(v1.y, n1, acc.y);
        acc.z = fmaf(v1.z, n1, acc.z); acc.w = fmaf(v1.w, n1, acc.w);
        acc.x = fmaf(v2.x, n2, acc.x); acc.y = fmaf(v2.y, n2, acc.y);
        acc.z = fmaf(v2.z, n2, acc.z); acc.w = fmaf(v2.w, n2, acc.w);
        acc.x = fmaf(v3.x, n3, acc.x); acc.y = fmaf(v3.y, n3, acc.y);
        acc.z = fmaf(v3.z, n3, acc.z); acc.w = fmaf(v3.w, n3, acc.w);
    }
    for (; j < end; j++) {
        int s0 = __ldg(&csrc[j]);
        float n0 = __ldg(&cnrm[j]);
        float4 v0 = X4[(size_t)s0 * 32 + lane];
        acc.x = fmaf(v0.x, n0, acc.x); acc.y = fmaf(v0.y, n0, acc.y);
        acc.z = fmaf(v0.z, n0, acc.z); acc.w = fmaf(v0.w, n0, acc.w);
    }
    float di = dinv[node];
    float sw = 2.0f * di * di;
    float4 xv = X4[(size_t)node * 32 + lane];
    float4 bv = ((const float4*)bias)[lane];
    acc.x = fast_tanh(fmaf(xv.x, sw, acc.x) + bv.x);
    acc.y = fast_tanh(fmaf(xv.y, sw, acc.y) + bv.y);
    acc.z = fast_tanh(fmaf(xv.z, sw, acc.z) + bv.z);
    acc.w = fast_tanh(fmaf(xv.w, sw, acc.w) + bv.w);
    ((float4*)out)[(size_t)node * 32 + lane] = acc;
}

// ---------------- GEMM [n,128] @ [128,128] via packed fma.rn.f32x2 ----------------
// 512 threads = 16 warps; each warp computes 8 nodes. W (64KB) + duplicated H
// rows (128KB) staged in smem. Channel pairs packed into 64-bit accumulators.
#define GR 8            // rows (nodes) per warp
#define GWARPS 16
#define GBLK (GR * GWARPS)   // 128 nodes per block
#define GSMEM ((16384 + GWARPS * GR * 256) * 4)   // W + Hdup, bytes

template <bool TANH, bool BIAS>
__global__ void __launch_bounds__(512) gemm128(
    const float* __restrict__ in, const float* __restrict__ W,
    const float* __restrict__ bias, float* __restrict__ out, int n)
{
    extern __shared__ float sm[];
    float4* Wsm4 = (float4*)sm;                    // 128x128 floats
    float*  Hdup = sm + 16384;                     // GWARPS * GR * 256 floats

    int tid = threadIdx.x, lane = tid & 31, w = tid >> 5;

    const float4* W4 = (const float4*)W;
    #pragma unroll
    for (int i = tid; i < 4096; i += 512) Wsm4[i] = W4[i];

    int nb = blockIdx.x * GBLK + w * GR;

    // stage this warp's 8 rows, each value duplicated (pairs for LDS.64 broadcast)
    float* Hw = Hdup + w * (GR * 256);
    #pragma unroll
    for (int j = 0; j < GR; j++) {
        int node = nb + j < n ? nb + j : (n - 1);
        float4 v = ((const float4*)in)[(size_t)node * 32 + lane];
        float* dst = Hw + j * 256 + lane * 8;
        ((float2*)dst)[0] = make_float2(v.x, v.x);
        ((float2*)dst)[1] = make_float2(v.y, v.y);
        ((float2*)dst)[2] = make_float2(v.z, v.z);
        ((float2*)dst)[3] = make_float2(v.w, v.w);
    }
    __syncthreads();

    if (nb >= n) return;

    unsigned long long acc[2 * GR];
    {
        unsigned long long b01 = 0ull, b23 = 0ull;
        if (BIAS) {
            float4 bv = ((const float4*)bias)[lane];
            b01 = pack2(bv.x, bv.y);
            b23 = pack2(bv.z, bv.w);
        }
        #pragma unroll
        for (int j = 0; j < GR; j++) { acc[2 * j] = b01; acc[2 * j + 1] = b23; }
    }

    #pragma unroll 4
    for (int k = 0; k < 128; k++) {
        float4 wv = Wsm4[k * 32 + lane];
        unsigned long long w01 = pack2(wv.x, wv.y);
        unsigned long long w23 = pack2(wv.z, wv.w);
        #pragma unroll
        for (int j = 0; j < GR; j++) {
            unsigned long long hh = *(const unsigned long long*)(Hw + j * 256 + 2 * k);
            acc[2 * j]     = fma2(w01, hh, acc[2 * j]);
            acc[2 * j + 1] = fma2(w23, hh, acc[2 * j + 1]);
        }
    }

    #pragma unroll
    for (int j = 0; j < GR; j++) {
        int node = nb + j;
        if (node >= n) break;
        float2 lo = unpack2(acc[2 * j]);
        float2 hi = unpack2(acc[2 * j + 1]);
        float4 v = make_float4(lo.x, lo.y, hi.x, hi.y);
        if (TANH) {
            v.x = fast_tanh(v.x); v.y = fast_tanh(v.y);
            v.z = fast_tanh(v.z); v.w = fast_tanh(v.w);
        }
        ((float4*)out)[(size_t)node * 32 + lane] = v;
    }
}

// ---------------- final 128 -> 3 ----------------
__global__ void __launch_bounds__(256) out_k(
    const float* __restrict__ h, const float* __restrict__ lw4,
    const float* __restrict__ lb4, float* __restrict__ out, int n)
{
    int wid = (blockIdx.x * 256 + threadIdx.x) >> 5;
    int lane = threadIdx.x & 31;
    if (wid >= n) return;
    const float* row = h + (size_t)wid * 128;
    float a0 = 0.f, a1 = 0.f, a2 = 0.f;
    #pragma unroll
    for (int k = lane; k < 128; k += 32) {
        float hv = row[k];
        a0 = fmaf(hv, __ldg(&lw4[k * 3 + 0]), a0);
        a1 = fmaf(hv, __ldg(&lw4[k * 3 + 1]), a1);
        a2 = fmaf(hv, __ldg(&lw4[k * 3 + 2]), a2);
    }
    #pragma unroll
    for (int o = 16; o; o >>= 1) {
        a0 += __shfl_down_sync(0xffffffffu, a0, o);
        a1 += __shfl_down_sync(0xffffffffu, a1, o);
        a2 += __shfl_down_sync(0xffffffffu, a2, o);
    }
    if (lane == 0) {
        out[(size_t)wid * 3 + 0] = a0 + lb4[0];
        out[(size_t)wid * 3 + 1] = a1 + lb4[1];
        out[(size_t)wid * 3 + 2] = a2 + lb4[2];
    }
}

// ---------------- launch ----------------
extern "C" void kernel_launch(void* const* d_in, const int* in_sizes, int n_in,
                              void* d_out, int out_size)
{
    const float* x   = (const float*)d_in[0];
    const void*  ei  = d_in[1];
    const float* W1  = (const float*)d_in[2];
    const float* b1  = (const float*)d_in[3];
    const float* W2  = (const float*)d_in[4];
    const float* b2  = (const float*)d_in[5];
    const float* lw1 = (const float*)d_in[6];
    const float* lb1 = (const float*)d_in[7];
    const float* lw2 = (const float*)d_in[8];
    const float* lb2 = (const float*)d_in[9];
    const float* lw3 = (const float*)d_in[10];
    const float* lb3 = (const float*)d_in[11];
    const float* lw4 = (const float*)d_in[12];
    const float* lb4 = (const float*)d_in[13];
    float* out = (float*)d_out;

    int n = in_sizes[0] / H;
    long long E = (long long)in_sizes[1] / 2;

    float *pX, *pA, *pD, *pNrm;
    int *pDeg, *pOff, *pCur, *pSrc;
    cudaGetSymbolAddress((void**)&pX, g_X);
    cudaGetSymbolAddress((void**)&pA, g_A);
    cudaGetSymbolAddress((void**)&pD, g_dinv);
    cudaGetSymbolAddress((void**)&pDeg, g_deg);
    cudaGetSymbolAddress((void**)&pOff, g_off);
    cudaGetSymbolAddress((void**)&pCur, g_cur);
    cudaGetSymbolAddress((void**)&pSrc, g_csrc);
    cudaGetSymbolAddress((void**)&pNrm, g_cnrm);

    cudaFuncSetAttribute(gemm128<false, false>, cudaFuncAttributeMaxDynamicSharedMemorySize, GSMEM);
    cudaFuncSetAttribute(gemm128<true,  true>,  cudaFuncAttributeMaxDynamicSharedMemorySize, GSMEM);

    int gb  = (n + GBLK - 1) / GBLK;       // gemm blocks
    int nwb = (n + 7) / 8;                 // warp-per-node blocks
    int eb  = (int)((E + 255) / 256);      // thread-per-edge blocks

    // 0. dtype probe + CSR build
    detect_k<<<1, 256>>>((const int*)ei);
    zeroi_k<<<(100352 / 4 + 255) / 256, 256>>>((int4*)pDeg, 100352 / 4);
    deg_k<<<eb, 256>>>(ei, E, pDeg);
    dinv_k<<<(n + 255) / 256, 256>>>(pDeg, pD, n);
    scan_k<<<1, 1024>>>(pDeg, pOff, pCur, n);
    fill_k<<<eb, 256>>>(ei, E, pD, pCur, pSrc, pNrm);

    // conv1: X = x @ W1; A = tanh(gather(X) + self + b1)
    gemm128<false, false><<<gb, 512, GSMEM>>>(x, W1, nullptr, pX, n);
    aggregate_k<<<nwb, 256>>>(pX, pOff, pDeg, pSrc, pNrm, pD, b1, pA, n);

    // conv2
    gemm128<false, false><<<gb, 512, GSMEM>>>(pA, W2, nullptr, pX, n);
    aggregate_k<<<nwb, 256>>>(pX, pOff, pDeg, pSrc, pNrm, pD, b2, pA, n);

    // MLP head
    gemm128<true, true><<<gb, 512, GSMEM>>>(pA, lw1, lb1, pX, n);
    gemm128<true, true><<<gb, 512, GSMEM>>>(pX, lw2, lb2, pA, n);
    gemm128<true, true><<<gb, 512, GSMEM>>>(pA, lw3, lb3, pX, n);
    out_k<<<(n + 7) / 8, 256>>>(pX, lw4, lb4, out, n);
}

// round 5
// speedup vs baseline: 1.0046x; 1.0046x over previous
#include <cuda_runtime.h>
#include <cstdint>

#define NN 100000
#define EE 3200000
#define H 128

// ---------------- scratch (__device__ globals; allocation-free rule) ----------------
__device__ float g_X[(size_t)NN * H];   // 51.2 MB ping
__device__ float g_A[(size_t)NN * H];   // 51.2 MB pong
__device__ float g_dinv[NN];
__device__ int   g_deg[100352];         // padded for int4 zeroing
__device__ int   g_off[NN + 1];
__device__ int   g_cur[100352];
__device__ int   g_csrc[EE];            // CSR: src per incoming edge of dst
__device__ float g_cnrm[EE];            // CSR: norm per incoming edge
__device__ int   g_is64;

__device__ __forceinline__ float fast_tanh(float x) {
    float t = __expf(-2.0f * fabsf(x));
    float r = __fdividef(1.0f - t, 1.0f + t);
    return copysignf(r, x);
}

// ---------------- packed f32x2 helpers ----------------
__device__ __forceinline__ unsigned long long pack2(float lo, float hi) {
    unsigned long long r;
    asm("mov.b64 %0, {%1, %2};" : "=l"(r) : "f"(lo), "f"(hi));
    return r;
}
__device__ __forceinline__ unsigned long long fma2(unsigned long long a,
                                                   unsigned long long b,
                                                   unsigned long long c) {
    unsigned long long d;
    asm("fma.rn.f32x2 %0, %1, %2, %3;" : "=l"(d) : "l"(a), "l"(b), "l"(c));
    return d;
}
__device__ __forceinline__ float2 unpack2(unsigned long long v) {
    float2 f;
    asm("mov.b64 {%0, %1}, %2;" : "=f"(f.x), "=f"(f.y) : "l"(v));
    return f;
}

// ---------------- edge dtype detection (int32 vs int64) ----------------
__global__ void detect_k(const int* __restrict__ ei32) {
    __shared__ int nz;
    if (threadIdx.x == 0) nz = 0;
    __syncthreads();
    int c = 0;
    for (int k = threadIdx.x; k < 4096; k += blockDim.x)
        if (ei32[2 * k + 1] != 0) c++;
    atomicAdd(&nz, c);
    __syncthreads();
    if (threadIdx.x == 0) g_is64 = (nz == 0) ? 1 : 0;
}

__device__ __forceinline__ int edge_val(const void* ei, long long E, long long idx, int row) {
    if (g_is64) return (int)((const long long*)ei)[row ? E + idx : idx];
    return ((const int*)ei)[row ? E + idx : idx];
}

// ---------------- zero ints ----------------
__global__ void zeroi_k(int4* __restrict__ p, int n4) {
    int i = blockIdx.x * blockDim.x + threadIdx.x;
    if (i < n4) p[i] = make_int4(0, 0, 0, 0);
}

// ---------------- degree count ----------------
__global__ void deg_k(const void* __restrict__ ei, long long E, int* __restrict__ deg) {
    long long e = (long long)blockIdx.x * blockDim.x + threadIdx.x;
    if (e < E) atomicAdd(&deg[edge_val(ei, E, e, 1)], 1);
}

__global__ void dinv_k(const int* __restrict__ deg, float* __restrict__ dinv, int n) {
    int i = blockIdx.x * blockDim.x + threadIdx.x;
    if (i < n) dinv[i] = rsqrtf((float)deg[i] + 2.0f);   // improved self-loop: +2
}

// ---------------- single-block scan: deg -> off, cur ----------------
__global__ void __launch_bounds__(1024) scan_k(const int* __restrict__ deg,
                                               int* __restrict__ off,
                                               int* __restrict__ cur, int n) {
    __shared__ int part[1024];
    int t = threadIdx.x;
    int chunk = (n + 1023) / 1024;
    int lo = t * chunk, hi = lo + chunk < n ? lo + chunk : n;
    int s = 0;
    for (int i = lo; i < hi; i++) s += deg[i];
    part[t] = s;
    __syncthreads();
    for (int o = 1; o < 1024; o <<= 1) {
        int v = (t >= o) ? part[t - o] : 0;
        __syncthreads();
        part[t] += v;
        __syncthreads();
    }
    int base = (t == 0) ? 0 : part[t - 1];
    for (int i = lo; i < hi; i++) {
        off[i] = base; cur[i] = base; base += deg[i];
    }
    if (t == 0) off[n] = part[1023];
}

// ---------------- CSR fill ----------------
__global__ void fill_k(const void* __restrict__ ei, long long E,
                       const float* __restrict__ dinv,
                       int* __restrict__ cur, int* __restrict__ csrc,
                       float* __restrict__ cnrm) {
    long long e = (long long)blockIdx.x * blockDim.x + threadIdx.x;
    if (e >= E) return;
    int s = edge_val(ei, E, e, 0);
    int d = edge_val(ei, E, e, 1);
    int pos = atomicAdd(&cur[d], 1);
    csrc[pos] = s;
    cnrm[pos] = dinv[s] * dinv[d];
}

// ---------------- gather + conv epilogue: out = tanh(sum + xw*2dinv^2 + b) ----------------
__global__ void __launch_bounds__(256) aggregate_k(
    const float* __restrict__ xw, const int* __restrict__ off,
    const int* __restrict__ deg, const int* __restrict__ csrc,
    const float* __restrict__ cnrm, const float* __restrict__ dinv,
    const float* __restrict__ bias, float* __restrict__ out, int n)
{
    int node = (blockIdx.x * 256 + threadIdx.x) >> 5;
    int lane = threadIdx.x & 31;
    if (node >= n) return;
    int j = off[node];
    int end = j + deg[node];
    const float4* X4 = (const float4*)xw;
    float4 acc = make_float4(0.f, 0.f, 0.f, 0.f);
    for (; j + 3 < end; j += 4) {
        int s0 = __ldg(&csrc[j]);     int s1 = __ldg(&csrc[j + 1]);
        int s2 = __ldg(&csrc[j + 2]); int s3 = __ldg(&csrc[j + 3]);
        float n0 = __ldg(&cnrm[j]);   float n1 = __ldg(&cnrm[j + 1]);
        float n2 = __ldg(&cnrm[j + 2]); float n3 = __ldg(&cnrm[j + 3]);
        float4 v0 = X4[(size_t)s0 * 32 + lane];
        float4 v1 = X4[(size_t)s1 * 32 + lane];
        float4 v2 = X4[(size_t)s2 * 32 + lane];
        float4 v3 = X4[(size_t)s3 * 32 + lane];
        acc.x = fmaf(v0.x, n0, acc.x); acc.y = fmaf(v0.y, n0, acc.y);
        acc.z = fmaf(v0.z, n0, acc.z); acc.w = fmaf(v0.w, n0, acc.w);
        acc.x = fmaf(v1.x, n1, acc.x); acc.y = fmaf(v1.y, n1, acc.y);
        acc.z = fmaf(v1.z, n1, acc.z); acc.w = fmaf(v1.w, n1, acc.w);
        acc.x = fmaf(v2.x, n2, acc.x); acc.y = fmaf(v2.y, n2, acc.y);
        acc.z = fmaf(v2.z, n2, acc.z); acc.w = fmaf(v2.w, n2, acc.w);
        acc.x = fmaf(v3.x, n3, acc.x); acc.y = fmaf(v3.y, n3, acc.y);
        acc.z = fmaf(v3.w == 0.f && false ? 0.f : v3.z, n3, acc.z); acc.w = fmaf(v3.w, n3, acc.w);
    }
    for (; j < end; j++) {
        int s0 = __ldg(&csrc[j]);
        float n0 = __ldg(&cnrm[j]);
        float4 v0 = X4[(size_t)s0 * 32 + lane];
        acc.x = fmaf(v0.x, n0, acc.x); acc.y = fmaf(v0.y, n0, acc.y);
        acc.z = fmaf(v0.z, n0, acc.z); acc.w = fmaf(v0.w, n0, acc.w);
    }
    float di = dinv[node];
    float sw = 2.0f * di * di;
    float4 xv = X4[(size_t)node * 32 + lane];
    float4 bv = ((const float4*)bias)[lane];
    acc.x = fast_tanh(fmaf(xv.x, sw, acc.x) + bv.x);
    acc.y = fast_tanh(fmaf(xv.y, sw, acc.y) + bv.y);
    acc.z = fast_tanh(fmaf(xv.z, sw, acc.z) + bv.z);
    acc.w = fast_tanh(fmaf(xv.w, sw, acc.w) + bv.w);
    ((float4*)out)[(size_t)node * 32 + lane] = acc;
}

// ---------------- GEMM [n,128] @ [128,128], outer-product tiling + fma.rn.f32x2 ----------
// 256 threads; CTA tile 128 rows x 128 cols; thread tile 8x8 (32 f32x2 accs).
// A staged in smem pre-duplicated as (a,a) float2 pairs; W staged natural.
#define GT_SMEM (128 * 128 * 8 + 128 * 128 * 4)   // Adup 128KB + W 64KB = 196608B

template <bool TANH, bool BIAS>
__global__ void __launch_bounds__(256) gemm128(
    const float* __restrict__ in, const float* __restrict__ W,
    const float* __restrict__ bias, float* __restrict__ out, int n)
{
    extern __shared__ float sm[];
    float2* Adup = (float2*)sm;                    // [128 rows][128 k] (a,a) pairs
    float*  Wsm  = sm + 128 * 128 * 2;             // [128 k][128 c]

    int tid = threadIdx.x;
    int rg = tid >> 4;          // 0..15 : rows rg*8 .. rg*8+7
    int cg = tid & 15;          // 0..15 : cols cg*8 .. cg*8+7
    int nb = blockIdx.x * 128;

    // stage A duplicated
    const float4* In4 = (const float4*)in;
    #pragma unroll
    for (int i = tid; i < 4096; i += 256) {
        int row = i >> 5, kq = i & 31;
        int node = nb + row < n ? nb + row : n - 1;
        float4 v = In4[(size_t)node * 32 + kq];
        float2* d = &Adup[row * 128 + kq * 4];
        d[0] = make_float2(v.x, v.x);
        d[1] = make_float2(v.y, v.y);
        d[2] = make_float2(v.z, v.z);
        d[3] = make_float2(v.w, v.w);
    }
    // stage W natural (row-major [k][c])
    const float4* W4 = (const float4*)W;
    float4* Wsm4 = (float4*)Wsm;
    #pragma unroll
    for (int i = tid; i < 4096; i += 256) Wsm4[i] = W4[i];
    __syncthreads();

    // accumulators: 8 rows x 4 col-pairs
    unsigned long long acc[8][4];
    {
        unsigned long long i0 = 0ull, i1 = 0ull, i2 = 0ull, i3 = 0ull;
        if (BIAS) {
            float4 bv0 = ((const float4*)bias)[cg * 2];
            float4 bv1 = ((const float4*)bias)[cg * 2 + 1];
            i0 = pack2(bv0.x, bv0.y); i1 = pack2(bv0.z, bv0.w);
            i2 = pack2(bv1.x, bv1.y); i3 = pack2(bv1.z, bv1.w);
        }
        #pragma unroll
        for (int r = 0; r < 8; r++) {
            acc[r][0] = i0; acc[r][1] = i1; acc[r][2] = i2; acc[r][3] = i3;
        }
    }

    const float2* Arow = Adup + rg * 8 * 128;   // this thread's first row
    const float*  Wc   = Wsm + cg * 8;          // this thread's first col

    #pragma unroll 2
    for (int kk = 0; kk < 128; kk += 2) {
        // A frags: (a,a) pairs for k=kk and kk+1, 8 rows (LDS.128, warp-broadcast)
        ulonglong2 a[8];
        #pragma unroll
        for (int r = 0; r < 8; r++)
            a[r] = *(const ulonglong2*)(Arow + r * 128 + kk);
        // B frags: 8 cols for k=kk and kk+1 (LDS.128 x4)
        ulonglong2 b0 = *(const ulonglong2*)(Wc + kk * 128);
        ulonglong2 b1 = *(const ulonglong2*)(Wc + kk * 128 + 4);
        ulonglong2 c0 = *(const ulonglong2*)(Wc + (kk + 1) * 128);
        ulonglong2 c1 = *(const ulonglong2*)(Wc + (kk + 1) * 128 + 4);
        #pragma unroll
        for (int r = 0; r < 8; r++) {
            acc[r][0] = fma2(a[r].x, b0.x, acc[r][0]);
            acc[r][1] = fma2(a[r].x, b0.y, acc[r][1]);
            acc[r][2] = fma2(a[r].x, b1.x, acc[r][2]);
            acc[r][3] = fma2(a[r].x, b1.y, acc[r][3]);
            acc[r][0] = fma2(a[r].y, c0.x, acc[r][0]);
            acc[r][1] = fma2(a[r].y, c0.y, acc[r][1]);
            acc[r][2] = fma2(a[r].y, c1.x, acc[r][2]);
            acc[r][3] = fma2(a[r].y, c1.y, acc[r][3]);
        }
    }

    // epilogue
    #pragma unroll
    for (int r = 0; r < 8; r++) {
        int node = nb + rg * 8 + r;
        if (node >= n) break;
        float2 p0 = unpack2(acc[r][0]);
        float2 p1 = unpack2(acc[r][1]);
        float2 p2 = unpack2(acc[r][2]);
        float2 p3 = unpack2(acc[r][3]);
        float4 lo = make_float4(p0.x, p0.y, p1.x, p1.y);
        float4 hi = make_float4(p2.x, p2.y, p3.x, p3.y);
        if (TANH) {
            lo.x = fast_tanh(lo.x); lo.y = fast_tanh(lo.y);
            lo.z = fast_tanh(lo.z); lo.w = fast_tanh(lo.w);
            hi.x = fast_tanh(hi.x); hi.y = fast_tanh(hi.y);
            hi.z = fast_tanh(hi.z); hi.w = fast_tanh(hi.w);
        }
        float4* o4 = (float4*)(out + (size_t)node * 128 + cg * 8);
        o4[0] = lo;
        o4[1] = hi;
    }
}

// ---------------- final 128 -> 3 ----------------
__global__ void __launch_bounds__(256) out_k(
    const float* __restrict__ h, const float* __restrict__ lw4,
    const float* __restrict__ lb4, float* __restrict__ out, int n)
{
    int wid = (blockIdx.x * 256 + threadIdx.x) >> 5;
    int lane = threadIdx.x & 31;
    if (wid >= n) return;
    const float* row = h + (size_t)wid * 128;
    float a0 = 0.f, a1 = 0.f, a2 = 0.f;
    #pragma unroll
    for (int k = lane; k < 128; k += 32) {
        float hv = row[k];
        a0 = fmaf(hv, __ldg(&lw4[k * 3 + 0]), a0);
        a1 = fmaf(hv, __ldg(&lw4[k * 3 + 1]), a1);
        a2 = fmaf(hv, __ldg(&lw4[k * 3 + 2]), a2);
    }
    #pragma unroll
    for (int o = 16; o; o >>= 1) {
        a0 += __shfl_down_sync(0xffffffffu, a0, o);
        a1 += __shfl_down_sync(0xffffffffu, a1, o);
        a2 += __shfl_down_sync(0xffffffffu, a2, o);
    }
    if (lane == 0) {
        out[(size_t)wid * 3 + 0] = a0 + lb4[0];
        out[(size_t)wid * 3 + 1] = a1 + lb4[1];
        out[(size_t)wid * 3 + 2] = a2 + lb4[2];
    }
}

// ---------------- launch ----------------
extern "C" void kernel_launch(void* const* d_in, const int* in_sizes, int n_in,
                              void* d_out, int out_size)
{
    const float* x   = (const float*)d_in[0];
    const void*  ei  = d_in[1];
    const float* W1  = (const float*)d_in[2];
    const float* b1  = (const float*)d_in[3];
    const float* W2  = (const float*)d_in[4];
    const float* b2  = (const float*)d_in[5];
    const float* lw1 = (const float*)d_in[6];
    const float* lb1 = (const float*)d_in[7];
    const float* lw2 = (const float*)d_in[8];
    const float* lb2 = (const float*)d_in[9];
    const float* lw3 = (const float*)d_in[10];
    const float* lb3 = (const float*)d_in[11];
    const float* lw4 = (const float*)d_in[12];
    const float* lb4 = (const float*)d_in[13];
    float* out = (float*)d_out;

    int n = in_sizes[0] / H;
    long long E = (long long)in_sizes[1] / 2;

    float *pX, *pA, *pD, *pNrm;
    int *pDeg, *pOff, *pCur, *pSrc;
    cudaGetSymbolAddress((void**)&pX, g_X);
    cudaGetSymbolAddress((void**)&pA, g_A);
    cudaGetSymbolAddress((void**)&pD, g_dinv);
    cudaGetSymbolAddress((void**)&pDeg, g_deg);
    cudaGetSymbolAddress((void**)&pOff, g_off);
    cudaGetSymbolAddress((void**)&pCur, g_cur);
    cudaGetSymbolAddress((void**)&pSrc, g_csrc);
    cudaGetSymbolAddress((void**)&pNrm, g_cnrm);

    cudaFuncSetAttribute(gemm128<false, false>, cudaFuncAttributeMaxDynamicSharedMemorySize, GT_SMEM);
    cudaFuncSetAttribute(gemm128<true,  true>,  cudaFuncAttributeMaxDynamicSharedMemorySize, GT_SMEM);

    int gb  = (n + 127) / 128;             // gemm blocks
    int nwb = (n + 7) / 8;                 // warp-per-node blocks
    int eb  = (int)((E + 255) / 256);      // thread-per-edge blocks

    // 0. dtype probe + CSR build
    detect_k<<<1, 256>>>((const int*)ei);
    zeroi_k<<<(100352 / 4 + 255) / 256, 256>>>((int4*)pDeg, 100352 / 4);
    deg_k<<<eb, 256>>>(ei, E, pDeg);
    dinv_k<<<(n + 255) / 256, 256>>>(pDeg, pD, n);
    scan_k<<<1, 1024>>>(pDeg, pOff, pCur, n);
    fill_k<<<eb, 256>>>(ei, E, pD, pCur, pSrc, pNrm);

    // conv1: X = x @ W1; A = tanh(gather(X) + self + b1)
    gemm128<false, false><<<gb, 256, GT_SMEM>>>(x, W1, nullptr, pX, n);
    aggregate_k<<<nwb, 256>>>(pX, pOff, pDeg, pSrc, pNrm, pD, b1, pA, n);

    // conv2
    gemm128<false, false><<<gb, 256, GT_SMEM>>>(pA, W2, nullptr, pX, n);
    aggregate_k<<<nwb, 256>>>(pX, pOff, pDeg, pSrc, pNrm, pD, b2, pA, n);

    // MLP head
    gemm128<true, true><<<gb, 256, GT_SMEM>>>(pA, lw1, lb1, pX, n);
    gemm128<true, true><<<gb, 256, GT_SMEM>>>(pX, lw2, lb2, pA, n);
    gemm128<true, true><<<gb, 256, GT_SMEM>>>(pA, lw3, lb3, pX, n);
    out_k<<<(n + 7) / 8, 256>>>(pX, lw4, lb4, out, n);
}